// round 14
// baseline (speedup 1.0000x reference)
#include <cuda_runtime.h>

#define NN 256
#define BB 2
#define NNODE (BB*NN)
#define NBLK 148

#define RSQRT3 0.5773502691896258f
#define INV_FAN 0.1767766952966369f   // 1/sqrt(32)

// partial G: per (node, half) -> [f*4+c], f in [0,33), f==32 = bias feature
__device__ float g_G2[2*NNODE][132];

#define PACK_F32X2(out, lo, hi) \
    asm("mov.b64 %0, {%1, %2};" : "=l"(out) : "f"(lo), "f"(hi))
#define UNPACK_F32X2(lo, hi, in) \
    asm("mov.b64 {%0, %1}, %2;" : "=f"(lo), "=f"(hi) : "l"(in))
#define FMA_F32X2(d, a, b, c) \
    asm("fma.rn.f32x2 %0, %1, %2, %3;" : "=l"(d) : "l"(a), "l"(b), "l"(c))
#define ADD_F32X2(d, a, b) \
    asm("add.rn.f32x2 %0, %1, %2;" : "=l"(d) : "l"(a), "l"(b))

#define CP_ASYNC16(dst_u32, src_ptr) \
    asm volatile("cp.async.ca.shared.global [%0], [%1], 16;" :: "r"(dst_u32), "l"(src_ptr))
#define CP_COMMIT() asm volatile("cp.async.commit_group;" ::: "memory")
#define CP_WAIT1()  asm volatile("cp.async.wait_group 1;" ::: "memory")
#define CP_WAIT0()  asm volatile("cp.async.wait_group 0;" ::: "memory")

// ---------------------------------------------------------------------------
// Kernel A (R6 winner, verbatim): edge reduction, block per (node, half).
// ---------------------------------------------------------------------------
__global__ __launch_bounds__(256, 4) void edge_kernel(
    const float* __restrict__ edge_attr,
    const float* __restrict__ edge_sh,
    const float* __restrict__ mask,
    const float* __restrict__ fc_w1,
    const float* __restrict__ fc_b1)
{
    __shared__ __align__(16) float ea[2][64 * 32];
    __shared__ __align__(16) float sh[128 * 4];
    __shared__ float w1s[32 * 32];
    __shared__ float b1s[32];
    __shared__ float Gp[8][132];

    const int blk  = blockIdx.x;
    const int node = blk >> 1;
    const int half = blk & 1;
    const int b = node >> 8;
    const int n = node & 255;
    const int m0 = half * 128;
    const int t = threadIdx.x;

    const float* ea_g = edge_attr + (size_t)node * NN * 32 + (size_t)m0 * 32;
    const unsigned ea_u = (unsigned)__cvta_generic_to_shared(&ea[0][0]);

    CP_ASYNC16(ea_u + (unsigned)t * 16u, ea_g + t * 4);
    CP_ASYNC16(ea_u + 4096u + (unsigned)t * 16u, ea_g + 1024 + t * 4);
    CP_COMMIT();
    CP_ASYNC16(ea_u + 8192u + (unsigned)t * 16u, ea_g + 2048 + t * 4);
    CP_ASYNC16(ea_u + 12288u + (unsigned)t * 16u, ea_g + 3072 + t * 4);
    CP_COMMIT();

    for (int i = t; i < 1024; i += 256) w1s[i] = fc_w1[i];
    if (t < 32) b1s[t] = fc_b1[t];
    if (t < 128) {
        int m = m0 + t;
        float mf = mask[b * NN + m] * (m != n ? 1.0f : 0.0f);
        float4 s = ((const float4*)(edge_sh + (size_t)node * NN * 4))[m];
        s.x *= mf; s.y *= mf; s.z *= mf; s.w *= mf;
        ((float4*)sh)[t] = s;
    }
    __syncthreads();

    const int f  = t & 31;
    const int mg = t >> 5;

    unsigned long long w1p[16];
    #pragma unroll
    for (int j = 0; j < 16; j++)
        PACK_F32X2(w1p[j], w1s[(2*j) * 32 + f], w1s[(2*j+1) * 32 + f]);
    unsigned long long bias2;
    PACK_F32X2(bias2, b1s[f], 0.0f);

    unsigned long long acc01 = 0ULL, acc23 = 0ULL;
    const ulonglong2* sh2 = (const ulonglong2*)sh;

    #pragma unroll
    for (int ch = 0; ch < 2; ch++) {
        if (ch == 0) { CP_WAIT1(); } else { CP_WAIT0(); }
        __syncthreads();
        const float* buf = ea[ch];
        #pragma unroll
        for (int it = 0; it < 8; it++) {
            int r = mg + it * 8;
            const ulonglong2* row = (const ulonglong2*)(buf + r * 32);
            unsigned long long c0 = bias2, c1 = 0ULL;
            ulonglong2 u0 = row[0];
            ulonglong2 u1 = row[1];
            ulonglong2 u2 = row[2];
            ulonglong2 u3 = row[3];
            FMA_F32X2(c0, u0.x, w1p[0], c0);
            FMA_F32X2(c1, u0.y, w1p[1], c1);
            FMA_F32X2(c0, u1.x, w1p[2], c0);
            FMA_F32X2(c1, u1.y, w1p[3], c1);
            u0 = row[4];
            u1 = row[5];
            FMA_F32X2(c0, u2.x, w1p[4], c0);
            FMA_F32X2(c1, u2.y, w1p[5], c1);
            FMA_F32X2(c0, u3.x, w1p[6], c0);
            FMA_F32X2(c1, u3.y, w1p[7], c1);
            u2 = row[6];
            u3 = row[7];
            FMA_F32X2(c0, u0.x, w1p[8],  c0);
            FMA_F32X2(c1, u0.y, w1p[9],  c1);
            FMA_F32X2(c0, u1.x, w1p[10], c0);
            FMA_F32X2(c1, u1.y, w1p[11], c1);
            FMA_F32X2(c0, u2.x, w1p[12], c0);
            FMA_F32X2(c1, u2.y, w1p[13], c1);
            FMA_F32X2(c0, u3.x, w1p[14], c0);
            FMA_F32X2(c1, u3.y, w1p[15], c1);
            ADD_F32X2(c0, c0, c1);
            float lo, hi;
            UNPACK_F32X2(lo, hi, c0);
            float h = fmaxf(lo + hi, 0.0f);
            unsigned long long h2;
            PACK_F32X2(h2, h, h);
            ulonglong2 s2 = sh2[ch * 64 + r];
            FMA_F32X2(acc01, h2, s2.x, acc01);
            FMA_F32X2(acc23, h2, s2.y, acc23);
        }
    }

    float o0, o1, o2, o3;
    UNPACK_F32X2(o0, o1, acc01);
    UNPACK_F32X2(o2, o3, acc23);
    Gp[mg][f*4+0] = o0;
    Gp[mg][f*4+1] = o1;
    Gp[mg][f*4+2] = o2;
    Gp[mg][f*4+3] = o3;

    if (t < 32) {
        int c = t & 3, mq = t >> 2;
        float s = 0.f;
        #pragma unroll 8
        for (int m = mq; m < 128; m += 8) s += sh[m * 4 + c];
        Gp[mq][128 + c] = s;
    }
    __syncthreads();

    if (t < 132) {
        float s = 0.f;
        #pragma unroll
        for (int g = 0; g < 8; g++) s += Gp[g][t];
        g_G2[blk][t] = s;
    }
}

// ---------------------------------------------------------------------------
// Kernel B: PERSISTENT node kernel. 148 blocks x 512 threads, 1 block/SM.
// All of W2' (33x1024 incl. bias row) staged in smem ONCE, then loop over
// nodes (block i handles nodes i, i+148, ...). No W2 re-reads, 4 barriers/node.
// ---------------------------------------------------------------------------
// smem float offsets
#define NOFF_W2S   0          // 33 x 1024
#define NOFF_PART  33792      // 64 x 68
#define NOFF_WLS   38144
#define NOFF_WLV   38400
#define NOFF_WOS   38656
#define NOFF_WOV   38912
#define NOFF_GS    39168      // 132 (16B aligned)
#define NOFF_SIN   39304      // 16
#define NOFF_VIN   39320      // 48
#define NOFF_OUTS  39368      // 16
#define NOFF_OUTV  39384      // 48
#define NOFF_RED   39432      // 16
#define NOFF_DSUM  39448      // 2
#define NSMEM_FLOATS 39452
#define NSMEM_BYTES (NSMEM_FLOATS * 4)

__device__ __forceinline__ void pairc(
    const float* __restrict__ sm, int f, int i, int oh,
    float si, float x0, float x1, float x2,
    unsigned long long& accS, unsigned long long accV[3])
{
    const float* Wb = sm + NOFF_W2S + f * 1024 + i * 16 + oh * 2;
    unsigned long long wss = *(const unsigned long long*)(Wb);
    unsigned long long wvv = *(const unsigned long long*)(Wb + 256);
    unsigned long long wsv = *(const unsigned long long*)(Wb + 512);
    unsigned long long wvs = *(const unsigned long long*)(Wb + 768);
    float4 gv = *(const float4*)(sm + NOFF_GS + f * 4);
    float a  = gv.x * si;
    float bc = (gv.y * x0 + gv.z * x1 + gv.w * x2) * RSQRT3;
    float c0 = gv.y * si, c1 = gv.z * si, c2 = gv.w * si;
    float d0 = gv.x * x0, d1 = gv.x * x1, d2 = gv.x * x2;
    unsigned long long a2, bc2, p0, p1, p2, q0, q1, q2;
    PACK_F32X2(a2, a, a);    PACK_F32X2(bc2, bc, bc);
    PACK_F32X2(p0, c0, c0);  PACK_F32X2(p1, c1, c1);  PACK_F32X2(p2, c2, c2);
    PACK_F32X2(q0, d0, d0);  PACK_F32X2(q1, d1, d1);  PACK_F32X2(q2, d2, d2);
    FMA_F32X2(accS, a2,  wss, accS);
    FMA_F32X2(accS, bc2, wvv, accS);
    FMA_F32X2(accV[0], p0, wsv, accV[0]);
    FMA_F32X2(accV[0], q0, wvs, accV[0]);
    FMA_F32X2(accV[1], p1, wsv, accV[1]);
    FMA_F32X2(accV[1], q1, wvs, accV[1]);
    FMA_F32X2(accV[2], p2, wsv, accV[2]);
    FMA_F32X2(accV[2], q2, wvs, accV[2]);
}

__global__ __launch_bounds__(512, 1) void node_kernel(
    const float* __restrict__ node_attr,
    const float* __restrict__ mask,
    const float* __restrict__ w_lin_in_s,
    const float* __restrict__ w_lin_in_v,
    const float* __restrict__ fc_w2,
    const float* __restrict__ fc_b2,
    const float* __restrict__ w_lin_out_s,
    const float* __restrict__ w_lin_out_v,
    float* __restrict__ out)
{
    extern __shared__ __align__(16) float sm[];
    const int t = threadIdx.x;
    const int wid = t >> 5;
    const int lane = t & 31;
    const unsigned sm_u = (unsigned)__cvta_generic_to_shared(sm);

    // ---- stage all of W2' (fc_w2 32x1024 + fc_b2 as row 32) ----
    for (int u = t; u < 8448; u += 512) {
        const float* src = (u < 8192) ? (fc_w2 + u * 4) : (fc_b2 + (u - 8192) * 4);
        CP_ASYNC16(sm_u + (unsigned)u * 16u, src);
    }
    CP_COMMIT();

    // ---- weights + dsum (overlaps the cp.async) ----
    if (t < 256) {
        sm[NOFF_WLS + t] = w_lin_in_s[t];
        sm[NOFF_WLV + t] = w_lin_in_v[t];
        sm[NOFF_WOS + t] = w_lin_out_s[t];
        sm[NOFF_WOV + t] = w_lin_out_v[t];
    }
    {
        float mv = mask[t];   // t in [0,512) covers both batches
        #pragma unroll
        for (int o = 16; o; o >>= 1) mv += __shfl_xor_sync(0xFFFFFFFFu, mv, o);
        if (lane == 0) sm[NOFF_RED + wid] = mv;
    }
    __syncthreads();
    if (t == 0) {
        float s0 = 0.f, s1 = 0.f;
        #pragma unroll
        for (int i = 0; i < 8; i++) { s0 += sm[NOFF_RED + i]; s1 += sm[NOFF_RED + 8 + i]; }
        sm[NOFF_DSUM + 0] = s0 - 1.0f;
        sm[NOFF_DSUM + 1] = s1 - 1.0f;
    }
    CP_WAIT0();

    const int p0 = t >> 3;     // pair slot [0,64)
    const int oh = t & 7;      // o-half
    const int i  = p0 & 15;    // invariant across k (64k = 0 mod 16)
    const int fb = p0 >> 4;    // f = fb + 4k

    // ---- persistent loop over nodes ----
    for (int n = blockIdx.x; n < NNODE; n += NBLK) {
        __syncthreads();   // guards smem reuse across iterations; also W2 visibility (after CP_WAIT0)
        if (t < 132) sm[NOFF_GS + t] = g_G2[n*2][t] + g_G2[n*2 + 1][t];
        if (t < 64) {
            const float* na = node_attr + (size_t)n * 64;
            if (t < 16) {
                float s = 0.f;
                #pragma unroll
                for (int ii = 0; ii < 16; ii++) s += na[ii] * sm[NOFF_WLS + ii * 16 + t];
                sm[NOFF_SIN + t] = s * 0.25f;
            } else {
                int idx = t - 16;
                int o = idx / 3, x = idx % 3;
                float s = 0.f;
                #pragma unroll
                for (int ii = 0; ii < 16; ii++) s += na[16 + ii * 3 + x] * sm[NOFF_WLV + ii * 16 + o];
                sm[NOFF_VIN + o * 3 + x] = s * 0.25f;
            }
        }
        __syncthreads();

        const float si = sm[NOFF_SIN + i];
        const float x0 = sm[NOFF_VIN + i * 3 + 0];
        const float x1 = sm[NOFF_VIN + i * 3 + 1];
        const float x2 = sm[NOFF_VIN + i * 3 + 2];

        unsigned long long accS = 0ULL;
        unsigned long long accV[3] = {0ULL, 0ULL, 0ULL};

        #pragma unroll
        for (int k = 0; k < 8; k++)
            pairc(sm, fb + 4 * k, i, oh, si, x0, x1, x2, accS, accV);
        if (p0 < 16)
            pairc(sm, 32, i, oh, si, x0, x1, x2, accS, accV);

        // stage partials: rows 0..15 = S(o), rows 16..63 = V(o,x); cols = p0
        {
            float v0, v1;
            UNPACK_F32X2(v0, v1, accS);
            sm[NOFF_PART + (oh * 2 + 0) * 68 + p0] = v0;
            sm[NOFF_PART + (oh * 2 + 1) * 68 + p0] = v1;
            #pragma unroll
            for (int x = 0; x < 3; x++) {
                UNPACK_F32X2(v0, v1, accV[x]);
                sm[NOFF_PART + (16 + (oh * 2 + 0) * 3 + x) * 68 + p0] = v0;
                sm[NOFF_PART + (16 + (oh * 2 + 1) * 3 + x) * 68 + p0] = v1;
            }
        }
        __syncthreads();

        // reduce 64 partials per output, scale
        if (t < 64) {
            float scale = INV_FAN / sm[NOFF_DSUM + (n >> 8)];
            const float4* row = (const float4*)(sm + NOFF_PART + t * 68);
            float s = 0.f;
            #pragma unroll
            for (int j = 0; j < 16; j++) {
                float4 v = row[j];
                s += (v.x + v.y) + (v.z + v.w);
            }
            if (t < 16) sm[NOFF_OUTS + t] = s * scale;
            else        sm[NOFF_OUTV + t - 16] = s * scale;
        }
        __syncthreads();

        // output linear (/4) + residual
        if (t < 64) {
            const float* na = node_attr + (size_t)n * 64;
            float r;
            if (t < 16) {
                float s = 0.f;
                #pragma unroll
                for (int o = 0; o < 16; o++) s += sm[NOFF_OUTS + o] * sm[NOFF_WOS + o * 16 + t];
                r = s * 0.25f + na[t];
            } else {
                int idx = t - 16;
                int o2 = idx / 3, x = idx % 3;
                float s = 0.f;
                #pragma unroll
                for (int o = 0; o < 16; o++) s += sm[NOFF_OUTV + o * 3 + x] * sm[NOFF_WOV + o * 16 + o2];
                r = s * 0.25f + na[t];
            }
            out[(size_t)n * 64 + t] = r;
        }
    }
}

extern "C" void kernel_launch(void* const* d_in, const int* in_sizes, int n_in,
                              void* d_out, int out_size) {
    const float* node_attr    = (const float*)d_in[0];
    const float* edge_attr    = (const float*)d_in[1];
    const float* edge_sh      = (const float*)d_in[2];
    const float* mask         = (const float*)d_in[3];
    const float* w_lin_in_s   = (const float*)d_in[4];
    const float* w_lin_in_v   = (const float*)d_in[5];
    const float* fc_w1        = (const float*)d_in[6];
    const float* fc_b1        = (const float*)d_in[7];
    const float* fc_w2        = (const float*)d_in[8];
    const float* fc_b2        = (const float*)d_in[9];
    const float* w_lin_out_s  = (const float*)d_in[10];
    const float* w_lin_out_v  = (const float*)d_in[11];
    float* out = (float*)d_out;

    cudaFuncSetAttribute(node_kernel,
                         cudaFuncAttributeMaxDynamicSharedMemorySize, NSMEM_BYTES);

    edge_kernel<<<2 * NNODE, 256>>>(edge_attr, edge_sh, mask, fc_w1, fc_b1);
    node_kernel<<<NBLK, 512, NSMEM_BYTES>>>(node_attr, mask,
                                    w_lin_in_s, w_lin_in_v,
                                    fc_w2, fc_b2, w_lin_out_s, w_lin_out_v, out);
}